// round 9
// baseline (speedup 1.0000x reference)
#include <cuda_runtime.h>
#include <math.h>

// Problem constants
#define BB 2
#define SS 1024
#define HID 2048
#define NH 32
#define NKV 8
#define HD 64
#define GROUP 4

#define OUT_ELEMS   (BB * SS * HID)             // 4,194,304
#define ATTN_ELEMS  ((size_t)BB * NH * SS * SS) // 67,108,864

// Scratch (device globals: no runtime allocation allowed)
__device__ float g_q[(size_t)BB * NH * SS * HD];
__device__ float g_k[(size_t)BB * NKV * SS * HD];
__device__ float g_v[(size_t)BB * NKV * SS * HD];
__device__ float g_ctx[(size_t)BB * SS * NH * HD];
__device__ float g_attn_fallback[ATTN_ELEMS];

// ---------------------------------------------------------------------------
// TF32 helpers
// ---------------------------------------------------------------------------
__device__ __forceinline__ unsigned f2tf(float f) {
    unsigned u;
    asm("cvt.rna.tf32.f32 %0, %1;" : "=r"(u) : "f"(f));
    return u;
}

__device__ __forceinline__ void mma_tf32(float c[4],
                                         unsigned a0, unsigned a1, unsigned a2, unsigned a3,
                                         unsigned b0, unsigned b1)
{
    asm volatile(
        "mma.sync.aligned.m16n8k8.row.col.f32.tf32.tf32.f32 "
        "{%0,%1,%2,%3},{%4,%5,%6,%7},{%8,%9},{%0,%1,%2,%3};"
        : "+f"(c[0]), "+f"(c[1]), "+f"(c[2]), "+f"(c[3])
        : "r"(a0), "r"(a1), "r"(a2), "r"(a3), "r"(b0), "r"(b1));
}

__device__ __forceinline__ void cpa16(void* s, const void* g) {
    unsigned sa = (unsigned)__cvta_generic_to_shared(s);
    asm volatile("cp.async.cg.shared.global [%0], [%1], 16;" :: "r"(sa), "l"(g));
}

// ---------------------------------------------------------------------------
// GEMM mainloop: 128x128 tile, BK=16, 2-stage cp.async double buffering.
// ---------------------------------------------------------------------------
#define AST 20
#define BST 136

__device__ __forceinline__ void gemm_mainloop(
    const float* __restrict__ Ab, const float* __restrict__ Wb,
    int N, int K, float acc[4][4][4], float* As, float* Bs)
{
    const int tid = threadIdx.x;
    const int warp = tid >> 5, lane = tid & 31;
    const int g = lane >> 2, t = lane & 3;
    const int wm = warp >> 2, wn = warp & 3;
    const int arow = tid >> 2, ac4 = (tid & 3) * 4;
    const int brow = tid >> 5, bn4 = (tid & 31) * 4;

    const int ntiles = K / 16;

    {
        cpa16(&As[arow * AST + ac4],        Ab + (size_t)arow * K + ac4);
        cpa16(&As[(arow + 64) * AST + ac4], Ab + (size_t)(arow + 64) * K + ac4);
        cpa16(&Bs[brow * BST + bn4],        Wb + (size_t)brow * N + bn4);
        cpa16(&Bs[(brow + 8) * BST + bn4],  Wb + (size_t)(brow + 8) * N + bn4);
        asm volatile("cp.async.commit_group;");
    }

    for (int i = 0; i < ntiles; i++) {
        if (i + 1 < ntiles) {
            const int k0 = (i + 1) * 16;
            float* An = As + ((i + 1) & 1) * 128 * AST;
            float* Bn = Bs + ((i + 1) & 1) * 16 * BST;
            cpa16(&An[arow * AST + ac4],        Ab + (size_t)arow * K + k0 + ac4);
            cpa16(&An[(arow + 64) * AST + ac4], Ab + (size_t)(arow + 64) * K + k0 + ac4);
            cpa16(&Bn[brow * BST + bn4],        Wb + (size_t)(k0 + brow) * N + bn4);
            cpa16(&Bn[(brow + 8) * BST + bn4],  Wb + (size_t)(k0 + brow + 8) * N + bn4);
            asm volatile("cp.async.commit_group;");
            asm volatile("cp.async.wait_group 1;");
        } else {
            asm volatile("cp.async.wait_group 0;");
        }
        __syncthreads();

        const float* Ac = As + (i & 1) * 128 * AST;
        const float* Bc = Bs + (i & 1) * 16 * BST;

#pragma unroll
        for (int kb = 0; kb < 16; kb += 8) {
            unsigned a[4][4], b[4][2];
#pragma unroll
            for (int mt = 0; mt < 4; mt++) {
                int rb = wm * 64 + mt * 16;
                a[mt][0] = f2tf(Ac[(rb + g) * AST + kb + t]);
                a[mt][1] = f2tf(Ac[(rb + g + 8) * AST + kb + t]);
                a[mt][2] = f2tf(Ac[(rb + g) * AST + kb + t + 4]);
                a[mt][3] = f2tf(Ac[(rb + g + 8) * AST + kb + t + 4]);
            }
#pragma unroll
            for (int nt = 0; nt < 4; nt++) {
                int cb = wn * 32 + nt * 8;
                b[nt][0] = f2tf(Bc[(kb + t) * BST + cb + g]);
                b[nt][1] = f2tf(Bc[(kb + t + 4) * BST + cb + g]);
            }
#pragma unroll
            for (int mt = 0; mt < 4; mt++)
#pragma unroll
                for (int nt = 0; nt < 4; nt++)
                    mma_tf32(acc[mt][nt], a[mt][0], a[mt][1], a[mt][2], a[mt][3],
                             b[nt][0], b[nt][1]);
        }
        __syncthreads();
    }
}

// ---------------------------------------------------------------------------
// Fused QKV projection: grid (24, 16). bn<16 -> Q, bn<20 -> K, else V.
// ---------------------------------------------------------------------------
__global__ __launch_bounds__(256, 2)
void qkv_kernel(const float* __restrict__ hidden,
                const float* __restrict__ wq, const float* __restrict__ wk,
                const float* __restrict__ wv,
                float* __restrict__ qo, float* __restrict__ ko,
                float* __restrict__ vo)
{
    __shared__ float As[2 * 128 * AST];
    __shared__ float Bs[2 * 16 * BST];

    const int bn = blockIdx.x, bm = blockIdx.y;
    const float* W; float* C; int N, nh, bl;
    if (bn < 16)      { W = wq; C = qo; N = 2048; nh = NH;  bl = bn; }
    else if (bn < 20) { W = wk; C = ko; N = 512;  nh = NKV; bl = bn - 16; }
    else              { W = wv; C = vo; N = 512;  nh = NKV; bl = bn - 20; }

    const float* Ab = hidden + (size_t)bm * 128 * 2048;
    const float* Wb = W + bl * 128;

    float acc[4][4][4];
#pragma unroll
    for (int i = 0; i < 4; i++)
#pragma unroll
        for (int j = 0; j < 4; j++)
#pragma unroll
            for (int r = 0; r < 4; r++) acc[i][j][r] = 0.f;

    gemm_mainloop(Ab, Wb, N, 2048, acc, As, Bs);

    const int tid = threadIdx.x;
    const int warp = tid >> 5, lane = tid & 31;
    const int g = lane >> 2, t = lane & 3;
    const int wm = warp >> 2, wn = warp & 3;

#pragma unroll
    for (int mt = 0; mt < 4; mt++)
#pragma unroll
        for (int nt = 0; nt < 4; nt++)
#pragma unroll
            for (int ri = 0; ri < 4; ri++) {
                int r = wm * 64 + mt * 16 + g + ((ri >= 2) ? 8 : 0);
                int c = wn * 32 + nt * 8 + 2 * t + (ri & 1);
                int m = bm * 128 + r, n = bl * 128 + c;
                int b_ = m >> 10, s = m & 1023;
                int head = n >> 6, dd = n & 63;
                C[(((size_t)b_ * nh + head) * SS + s) * HD + dd] = acc[mt][nt][ri];
            }
}

// ---------------------------------------------------------------------------
// Plain GEMM (out projection): C[m*N+n] = A @ W.
// ---------------------------------------------------------------------------
__global__ __launch_bounds__(256, 2)
void gemm_kernel(const float* __restrict__ A, const float* __restrict__ W,
                 float* __restrict__ C, int M, int N, int K)
{
    __shared__ float As[2 * 128 * AST];
    __shared__ float Bs[2 * 16 * BST];

    const int bn = blockIdx.x, bm = blockIdx.y;
    const float* Ab = A + (size_t)bm * 128 * K;
    const float* Wb = W + bn * 128;

    float acc[4][4][4];
#pragma unroll
    for (int i = 0; i < 4; i++)
#pragma unroll
        for (int j = 0; j < 4; j++)
#pragma unroll
            for (int r = 0; r < 4; r++) acc[i][j][r] = 0.f;

    gemm_mainloop(Ab, Wb, N, K, acc, As, Bs);

    const int tid = threadIdx.x;
    const int warp = tid >> 5, lane = tid & 31;
    const int g = lane >> 2, t = lane & 3;
    const int wm = warp >> 2, wn = warp & 3;

#pragma unroll
    for (int mt = 0; mt < 4; mt++)
#pragma unroll
        for (int nt = 0; nt < 4; nt++)
#pragma unroll
            for (int ri = 0; ri < 4; ri++) {
                int r = wm * 64 + mt * 16 + g + ((ri >= 2) ? 8 : 0);
                int c = wn * 32 + nt * 8 + 2 * t + (ri & 1);
                int m = bm * 128 + r, n = bn * 128 + c;
                C[(size_t)m * N + n] = acc[mt][nt][ri];
            }
}

// ---------------------------------------------------------------------------
// RoPE in place on (rows, 64) buffer; row % S = sequence position.
// ---------------------------------------------------------------------------
__global__ void rope_kernel(float* __restrict__ buf, int nrows,
                            const float* __restrict__ cosb,
                            const float* __restrict__ sinb)
{
    int idx = blockIdx.x * blockDim.x + threadIdx.x;
    if (idx >= nrows * 32) return;
    int row = idx >> 5;
    int d = idx & 31;
    int s = row & (SS - 1);
    float x1 = buf[(size_t)row * HD + d];
    float x2 = buf[(size_t)row * HD + d + 32];
    float c1 = cosb[s * HD + d],      s1 = sinb[s * HD + d];
    float c2 = cosb[s * HD + d + 32], s2 = sinb[s * HD + d + 32];
    buf[(size_t)row * HD + d]      = x1 * c1 - x2 * s1;
    buf[(size_t)row * HD + d + 32] = x2 * c2 + x1 * s2;
}

// ---------------------------------------------------------------------------
// Fused attention, two-sweep recompute scheme. Block = (z, 64-row q tile).
// Sweep 1: S = Q.K^T (K cp.async double-buffered), e = exp(S/8) masked,
//          row sums only -> invs.  Nothing written to gmem.
// Sweep 2: recompute S (K L2-hot), stage raw e in smem, write NORMALIZED attn
//          (coalesced float4, the only attn write), ctx mma from the same
//          smem tile; inv applied at the ctx epilogue.
// Upper-triangle zero-fill at the end. ~108 KB smem -> 2 CTAs/SM.
// ---------------------------------------------------------------------------
#define FQST 68
#define FKST 68
#define FVST 72
#define FSST 68
#define FA_SMEM ((64*FQST + 2*64*FKST + 2*64*FVST + 64*FSST + 1024 + 64) * 4)

__global__ __launch_bounds__(256, 2)
void attn_kernel(const float* __restrict__ q, const float* __restrict__ k,
                 const float* __restrict__ v, const float* __restrict__ mask,
                 float* __restrict__ attn, float* __restrict__ ctx)
{
    extern __shared__ float sm[];
    unsigned* Qs  = (unsigned*)sm;               // 64 x FQST (tf32)
    float*    Ksm = sm + 64 * FQST;              // 2 x 64 x FKST
    float*    Vsm = Ksm + 2 * 64 * FKST;         // 2 x 64 x FVST
    float*    Ss  = Vsm + 2 * 64 * FVST;         // 64 x FSST (raw e staging)
    float*    msk = Ss + 64 * FSST;              // 1024
    float*    invs = msk + 1024;                 // 64

    const int qt = 15 - blockIdx.x;              // heavy q-tiles first
    const int z  = blockIdx.y;
    const int b = z >> 5, h = z & 31, kvh = h >> 2;
    const int nkt = qt + 1;

    const int tid = threadIdx.x;
    const int warp = tid >> 5, lane = tid & 31;
    const int g = lane >> 2, t = lane & 3;
    const int wm = warp >> 2, wn = warp & 3;     // 2(m) x 4(n)

    const float* Qg = q + ((size_t)z * SS + qt * 64) * HD;
    const float* Kg = k + (size_t)(b * NKV + kvh) * SS * HD;
    const float* Vg = v + (size_t)(b * NKV + kvh) * SS * HD;
    float* P = attn + ((size_t)z * SS + qt * 64) * SS;

    // ---- Q -> tf32 smem (64x64); mask -> smem ----
#pragma unroll
    for (int l = 0; l < 4; l++) {
        int i4 = tid + l * 256;
        int row = i4 >> 4, c4 = (i4 & 15) * 4;
        float4 qv = *(const float4*)(Qg + (size_t)row * HD + c4);
        Qs[row * FQST + c4 + 0] = f2tf(qv.x);
        Qs[row * FQST + c4 + 1] = f2tf(qv.y);
        Qs[row * FQST + c4 + 2] = f2tf(qv.z);
        Qs[row * FQST + c4 + 3] = f2tf(qv.w);
    }
    for (int i = tid; i < nkt * 16; i += 256)
        ((float4*)msk)[i] = ((const float4*)(mask + (size_t)b * SS))[i];

    // per-thread output columns (fixed): c = wn*16 + nt*8 + 2t + lsb
    const int cbase = wn * 16 + 2 * t;

    // ================= SWEEP 1: row sums =================
    {
#pragma unroll
        for (int l = 0; l < 4; l++) {       // K tile 0 -> buf 0
            int i4 = tid + l * 256;
            int row = i4 >> 4, c4 = (i4 & 15) * 4;
            cpa16(&Ksm[row * FKST + c4], Kg + (size_t)row * HD + c4);
        }
        asm volatile("cp.async.commit_group;");
    }

    float rs[4] = {0.f, 0.f, 0.f, 0.f};

    for (int kt = 0; kt < nkt; kt++) {
        if (kt + 1 < nkt) {
            float* Kn = Ksm + ((kt + 1) & 1) * 64 * FKST;
            const float* Kgs = Kg + (size_t)(kt + 1) * 64 * HD;
#pragma unroll
            for (int l = 0; l < 4; l++) {
                int i4 = tid + l * 256;
                int row = i4 >> 4, c4 = (i4 & 15) * 4;
                cpa16(&Kn[row * FKST + c4], Kgs + (size_t)row * HD + c4);
            }
            asm volatile("cp.async.commit_group;");
            asm volatile("cp.async.wait_group 1;");
        } else {
            asm volatile("cp.async.wait_group 0;");
        }
        __syncthreads();

        const float* Kc = Ksm + (kt & 1) * 64 * FKST;

        float accs[2][2][4];
#pragma unroll
        for (int i = 0; i < 2; i++)
#pragma unroll
            for (int j = 0; j < 2; j++)
#pragma unroll
                for (int r = 0; r < 4; r++) accs[i][j][r] = 0.f;

#pragma unroll
        for (int kb = 0; kb < 64; kb += 8) {
            unsigned a[2][4], bf[2][2];
#pragma unroll
            for (int mt = 0; mt < 2; mt++) {
                int rb = wm * 32 + mt * 16;
                a[mt][0] = Qs[(rb + g) * FQST + kb + t];
                a[mt][1] = Qs[(rb + g + 8) * FQST + kb + t];
                a[mt][2] = Qs[(rb + g) * FQST + kb + t + 4];
                a[mt][3] = Qs[(rb + g + 8) * FQST + kb + t + 4];
            }
#pragma unroll
            for (int nt = 0; nt < 2; nt++) {
                int cb = wn * 16 + nt * 8;
                bf[nt][0] = f2tf(Kc[(cb + g) * FKST + kb + t]);
                bf[nt][1] = f2tf(Kc[(cb + g) * FKST + kb + t + 4]);
            }
#pragma unroll
            for (int mt = 0; mt < 2; mt++)
#pragma unroll
                for (int nt = 0; nt < 2; nt++)
                    mma_tf32(accs[mt][nt], a[mt][0], a[mt][1], a[mt][2], a[mt][3],
                             bf[nt][0], bf[nt][1]);
        }

#pragma unroll
        for (int mt = 0; mt < 2; mt++)
#pragma unroll
            for (int nt = 0; nt < 2; nt++)
#pragma unroll
                for (int ri = 0; ri < 4; ri++) {
                    int r = wm * 32 + mt * 16 + g + ((ri >= 2) ? 8 : 0);
                    int c = cbase + nt * 8 + (ri & 1);
                    int qg = qt * 64 + r, kg = kt * 64 + c;
                    bool ok = (kg <= qg) && (msk[kg] == 1.0f);
                    float e = ok ? __expf(accs[mt][nt][ri] * 0.125f) : 0.f;
                    rs[mt * 2 + (ri >> 1)] += e;
                }
        __syncthreads();
    }

    // sweep2 prologue: K0 + V0 (safe: all sweep1 reads done)
    {
#pragma unroll
        for (int l = 0; l < 4; l++) {
            int i4 = tid + l * 256;
            int row = i4 >> 4, c4 = (i4 & 15) * 4;
            cpa16(&Ksm[row * FKST + c4], Kg + (size_t)row * HD + c4);
            cpa16(&Vsm[row * FVST + c4], Vg + (size_t)row * HD + c4);
        }
        asm volatile("cp.async.commit_group;");
    }

    // ---- row sums -> invs (red buffer reuses Ss) ----
#pragma unroll
    for (int mt = 0; mt < 2; mt++)
#pragma unroll
        for (int hi = 0; hi < 2; hi++) {
            float vv = rs[mt * 2 + hi];
            vv += __shfl_xor_sync(0xffffffffu, vv, 1);
            vv += __shfl_xor_sync(0xffffffffu, vv, 2);
            if (t == 0)
                Ss[(wm * 32 + mt * 16 + hi * 8 + g) * 4 + wn] = vv;
        }
    __syncthreads();
    if (tid < 64) {
        float s = Ss[tid * 4] + Ss[tid * 4 + 1] + Ss[tid * 4 + 2] + Ss[tid * 4 + 3];
        invs[tid] = 1.0f / s;
    }
    __syncthreads();

    // ================= SWEEP 2: attn write + ctx =================
    float accc[2][2][4];
#pragma unroll
    for (int i = 0; i < 2; i++)
#pragma unroll
        for (int j = 0; j < 2; j++)
#pragma unroll
            for (int r = 0; r < 4; r++) accc[i][j][r] = 0.f;

    const int srow = tid >> 2;          // epilogue mapping: 4 threads per row
    const int sch0 = tid & 3;

    for (int kt = 0; kt < nkt; kt++) {
        if (kt + 1 < nkt) {
            float* Kn = Ksm + ((kt + 1) & 1) * 64 * FKST;
            float* Vn = Vsm + ((kt + 1) & 1) * 64 * FVST;
            const float* Kgs = Kg + (size_t)(kt + 1) * 64 * HD;
            const float* Vgs = Vg + (size_t)(kt + 1) * 64 * HD;
#pragma unroll
            for (int l = 0; l < 4; l++) {
                int i4 = tid + l * 256;
                int row = i4 >> 4, c4 = (i4 & 15) * 4;
                cpa16(&Kn[row * FKST + c4], Kgs + (size_t)row * HD + c4);
                cpa16(&Vn[row * FVST + c4], Vgs + (size_t)row * HD + c4);
            }
            asm volatile("cp.async.commit_group;");
            asm volatile("cp.async.wait_group 1;");
        } else {
            asm volatile("cp.async.wait_group 0;");
        }
        __syncthreads();

        const float* Kc = Ksm + (kt & 1) * 64 * FKST;
        const float* Vc = Vsm + (kt & 1) * 64 * FVST;

        // ---- S = Q.K^T ----
        float accs[2][2][4];
#pragma unroll
        for (int i = 0; i < 2; i++)
#pragma unroll
            for (int j = 0; j < 2; j++)
#pragma unroll
                for (int r = 0; r < 4; r++) accs[i][j][r] = 0.f;

#pragma unroll
        for (int kb = 0; kb < 64; kb += 8) {
            unsigned a[2][4], bf[2][2];
#pragma unroll
            for (int mt = 0; mt < 2; mt++) {
                int rb = wm * 32 + mt * 16;
                a[mt][0] = Qs[(rb + g) * FQST + kb + t];
                a[mt][1] = Qs[(rb + g + 8) * FQST + kb + t];
                a[mt][2] = Qs[(rb + g) * FQST + kb + t + 4];
                a[mt][3] = Qs[(rb + g + 8) * FQST + kb + t + 4];
            }
#pragma unroll
            for (int nt = 0; nt < 2; nt++) {
                int cb = wn * 16 + nt * 8;
                bf[nt][0] = f2tf(Kc[(cb + g) * FKST + kb + t]);
                bf[nt][1] = f2tf(Kc[(cb + g) * FKST + kb + t + 4]);
            }
#pragma unroll
            for (int mt = 0; mt < 2; mt++)
#pragma unroll
                for (int nt = 0; nt < 2; nt++)
                    mma_tf32(accs[mt][nt], a[mt][0], a[mt][1], a[mt][2], a[mt][3],
                             bf[nt][0], bf[nt][1]);
        }

        // ---- stage raw e into Ss ----
#pragma unroll
        for (int mt = 0; mt < 2; mt++)
#pragma unroll
            for (int nt = 0; nt < 2; nt++)
#pragma unroll
                for (int ri = 0; ri < 4; ri++) {
                    int r = wm * 32 + mt * 16 + g + ((ri >= 2) ? 8 : 0);
                    int c = cbase + nt * 8 + (ri & 1);
                    int qg = qt * 64 + r, kg = kt * 64 + c;
                    bool ok = (kg <= qg) && (msk[kg] == 1.0f);
                    Ss[r * FSST + c] = ok ? __expf(accs[mt][nt][ri] * 0.125f) : 0.f;
                }
        __syncthreads();

        // ---- normalized attn write (coalesced float4) ----
        {
            float iv = invs[srow];
            float* dst = P + (size_t)srow * SS + kt * 64;
            const float* src = &Ss[srow * FSST];
#pragma unroll
            for (int p = 0; p < 4; p++) {
                int ch = sch0 + p * 4;
                float4 e4 = *(const float4*)&src[ch * 4];
                e4.x *= iv; e4.y *= iv; e4.z *= iv; e4.w *= iv;
                *(float4*)(dst + ch * 4) = e4;
            }
        }

        // ---- ctx += e_tile . V_tile (raw e; inv at epilogue) ----
#pragma unroll
        for (int kb = 0; kb < 64; kb += 8) {
            unsigned a[2][4], bf[2][2];
#pragma unroll
            for (int mt = 0; mt < 2; mt++) {
                int rb = wm * 32 + mt * 16;
                a[mt][0] = f2tf(Ss[(rb + g) * FSST + kb + t]);
                a[mt][1] = f2tf(Ss[(rb + g + 8) * FSST + kb + t]);
                a[mt][2] = f2tf(Ss[(rb + g) * FSST + kb + t + 4]);
                a[mt][3] = f2tf(Ss[(rb + g + 8) * FSST + kb + t + 4]);
            }
#pragma unroll
            for (int nt = 0; nt < 2; nt++) {
                int cb = wn * 16 + nt * 8;
                bf[nt][0] = f2tf(Vc[(kb + t) * FVST + cb + g]);
                bf[nt][1] = f2tf(Vc[(kb + t + 4) * FVST + cb + g]);
            }
#pragma unroll
            for (int mt = 0; mt < 2; mt++)
#pragma unroll
                for (int nt = 0; nt < 2; nt++)
                    mma_tf32(accc[mt][nt], a[mt][0], a[mt][1], a[mt][2], a[mt][3],
                             bf[nt][0], bf[nt][1]);
        }
        __syncthreads();
    }

    // ---- ctx epilogue ----
#pragma unroll
    for (int mt = 0; mt < 2; mt++)
#pragma unroll
        for (int nt = 0; nt < 2; nt++)
#pragma unroll
            for (int ri = 0; ri < 4; ri++) {
                int r = wm * 32 + mt * 16 + g + ((ri >= 2) ? 8 : 0);
                int c = cbase + nt * 8 + (ri & 1);
                int qg = qt * 64 + r;
                ctx[((size_t)b * SS + qg) * HID + h * HD + c] =
                    accc[mt][nt][ri] * invs[r];
            }

    // ---- zero-fill upper triangle of this strip ----
    const int ckt4 = nkt * 16;                 // valid float4 chunks per row
    float4 zero = make_float4(0.f, 0.f, 0.f, 0.f);
    for (int i4 = tid; i4 < 64 * 256; i4 += 256) {
        int row = i4 >> 8, c4 = i4 & 255;
        if (c4 >= ckt4)
            *(float4*)(P + (size_t)row * SS + c4 * 4) = zero;
    }
}

// ---------------------------------------------------------------------------
extern "C" void kernel_launch(void* const* d_in, const int* in_sizes, int n_in,
                              void* d_out, int out_size)
{
    const float* hidden = (const float*)d_in[0];
    const float* mask   = (const float*)d_in[1];
    const float* cosb   = (const float*)d_in[2];
    const float* sinb   = (const float*)d_in[3];
    const float* wq     = (const float*)d_in[4];
    const float* wk     = (const float*)d_in[5];
    const float* wv     = (const float*)d_in[6];
    const float* wo     = (const float*)d_in[7];

    float* outp = (float*)d_out;

    float *qp, *kp, *vp, *cp;
    cudaGetSymbolAddress((void**)&qp, g_q);
    cudaGetSymbolAddress((void**)&kp, g_k);
    cudaGetSymbolAddress((void**)&vp, g_v);
    cudaGetSymbolAddress((void**)&cp, g_ctx);

    float* attnp;
    if ((size_t)out_size >= OUT_ELEMS + ATTN_ELEMS) {
        attnp = outp + OUT_ELEMS;
    } else {
        cudaGetSymbolAddress((void**)&attnp, g_attn_fallback);
    }

    cudaFuncSetAttribute(attn_kernel,
                         cudaFuncAttributeMaxDynamicSharedMemorySize, FA_SMEM);

    // 1) fused QKV projection (cp.async pipelined tf32)
    qkv_kernel<<<dim3(24, 16), 256>>>(hidden, wq, wk, wv, qp, kp, vp);

    // 2) RoPE on q and k
    rope_kernel<<<(BB * NH * SS * 32) / 256, 256>>>(qp, BB * NH * SS, cosb, sinb);
    rope_kernel<<<(BB * NKV * SS * 32) / 256, 256>>>(kp, BB * NKV * SS, cosb, sinb);

    // 3) fused two-sweep attention (single attn write)
    attn_kernel<<<dim3(16, BB * NH), 256, FA_SMEM>>>(qp, kp, vp, mask, attnp, cp);

    // 4) out = ctx @ wo
    gemm_kernel<<<dim3(16, 16), 256>>>(cp, wo, outp, 2048, 2048, 2048);
}

// round 10
// speedup vs baseline: 1.1230x; 1.1230x over previous
#include <cuda_runtime.h>
#include <math.h>

// Problem constants
#define BB 2
#define SS 1024
#define HID 2048
#define NH 32
#define NKV 8
#define HD 64
#define GROUP 4

#define OUT_ELEMS   (BB * SS * HID)             // 4,194,304
#define ATTN_ELEMS  ((size_t)BB * NH * SS * SS) // 67,108,864
#define NROWS       (BB * NH * SS)              // 65,536 attn rows
#define NKT         16                          // k-tiles per row

// Scratch (device globals: no runtime allocation allowed)
__device__ float g_q[(size_t)BB * NH * SS * HD];
__device__ float g_k[(size_t)BB * NKV * SS * HD];
__device__ float g_v[(size_t)BB * NKV * SS * HD];
__device__ float g_ctx[(size_t)BB * SS * NH * HD];
__device__ float g_part[(size_t)NROWS * NKT];
__device__ float g_inv[NROWS];
__device__ float g_attn_fallback[ATTN_ELEMS];

// ---------------------------------------------------------------------------
// TF32 helpers
// ---------------------------------------------------------------------------
__device__ __forceinline__ unsigned f2tf(float f) {
    unsigned u;
    asm("cvt.rna.tf32.f32 %0, %1;" : "=r"(u) : "f"(f));
    return u;
}

__device__ __forceinline__ void mma_tf32(float c[4],
                                         unsigned a0, unsigned a1, unsigned a2, unsigned a3,
                                         unsigned b0, unsigned b1)
{
    asm volatile(
        "mma.sync.aligned.m16n8k8.row.col.f32.tf32.tf32.f32 "
        "{%0,%1,%2,%3},{%4,%5,%6,%7},{%8,%9},{%0,%1,%2,%3};"
        : "+f"(c[0]), "+f"(c[1]), "+f"(c[2]), "+f"(c[3])
        : "r"(a0), "r"(a1), "r"(a2), "r"(a3), "r"(b0), "r"(b1));
}

__device__ __forceinline__ void cpa16(void* s, const void* g) {
    unsigned sa = (unsigned)__cvta_generic_to_shared(s);
    asm volatile("cp.async.cg.shared.global [%0], [%1], 16;" :: "r"(sa), "l"(g));
}

// ---------------------------------------------------------------------------
// GEMM mainloop: 128x128 tile, BK=16, 3-stage cp.async ring (2-tile lookahead).
// ---------------------------------------------------------------------------
#define AST 20
#define BST 136

__device__ __forceinline__ void gemm_mainloop(
    const float* __restrict__ Ab, const float* __restrict__ Wb,
    int N, int K, float acc[4][4][4], float* As, float* Bs)
{
    const int tid = threadIdx.x;
    const int warp = tid >> 5, lane = tid & 31;
    const int g = lane >> 2, t = lane & 3;
    const int wm = warp >> 2, wn = warp & 3;
    const int arow = tid >> 2, ac4 = (tid & 3) * 4;
    const int brow = tid >> 5, bn4 = (tid & 31) * 4;

    const int ntiles = K / 16;

    // prologue: stages 0 and 1
#pragma unroll
    for (int s = 0; s < 2; s++) {
        if (s < ntiles) {
            const int k0 = s * 16;
            float* An = As + s * 128 * AST;
            float* Bn = Bs + s * 16 * BST;
            cpa16(&An[arow * AST + ac4],        Ab + (size_t)arow * K + k0 + ac4);
            cpa16(&An[(arow + 64) * AST + ac4], Ab + (size_t)(arow + 64) * K + k0 + ac4);
            cpa16(&Bn[brow * BST + bn4],        Wb + (size_t)(k0 + brow) * N + bn4);
            cpa16(&Bn[(brow + 8) * BST + bn4],  Wb + (size_t)(k0 + brow + 8) * N + bn4);
            asm volatile("cp.async.commit_group;");
        }
    }

    for (int i = 0; i < ntiles; i++) {
        if (i + 2 < ntiles) {
            const int k0 = (i + 2) * 16;
            float* An = As + ((i + 2) % 3) * 128 * AST;
            float* Bn = Bs + ((i + 2) % 3) * 16 * BST;
            cpa16(&An[arow * AST + ac4],        Ab + (size_t)arow * K + k0 + ac4);
            cpa16(&An[(arow + 64) * AST + ac4], Ab + (size_t)(arow + 64) * K + k0 + ac4);
            cpa16(&Bn[brow * BST + bn4],        Wb + (size_t)(k0 + brow) * N + bn4);
            cpa16(&Bn[(brow + 8) * BST + bn4],  Wb + (size_t)(k0 + brow + 8) * N + bn4);
            asm volatile("cp.async.commit_group;");
            asm volatile("cp.async.wait_group 2;");
        } else if (i + 1 < ntiles) {
            asm volatile("cp.async.wait_group 1;");
        } else {
            asm volatile("cp.async.wait_group 0;");
        }
        __syncthreads();

        const float* Ac = As + (i % 3) * 128 * AST;
        const float* Bc = Bs + (i % 3) * 16 * BST;

#pragma unroll
        for (int kb = 0; kb < 16; kb += 8) {
            unsigned a[4][4], b[4][2];
#pragma unroll
            for (int mt = 0; mt < 4; mt++) {
                int rb = wm * 64 + mt * 16;
                a[mt][0] = f2tf(Ac[(rb + g) * AST + kb + t]);
                a[mt][1] = f2tf(Ac[(rb + g + 8) * AST + kb + t]);
                a[mt][2] = f2tf(Ac[(rb + g) * AST + kb + t + 4]);
                a[mt][3] = f2tf(Ac[(rb + g + 8) * AST + kb + t + 4]);
            }
#pragma unroll
            for (int nt = 0; nt < 4; nt++) {
                int cb = wn * 32 + nt * 8;
                b[nt][0] = f2tf(Bc[(kb + t) * BST + cb + g]);
                b[nt][1] = f2tf(Bc[(kb + t + 4) * BST + cb + g]);
            }
#pragma unroll
            for (int mt = 0; mt < 4; mt++)
#pragma unroll
                for (int nt = 0; nt < 4; nt++)
                    mma_tf32(acc[mt][nt], a[mt][0], a[mt][1], a[mt][2], a[mt][3],
                             b[nt][0], b[nt][1]);
        }
        __syncthreads();
    }
}

// ---------------------------------------------------------------------------
// Fused QKV projection: grid (24, 16). bn<16 -> Q, bn<20 -> K, else V.
// ---------------------------------------------------------------------------
__global__ __launch_bounds__(256, 2)
void qkv_kernel(const float* __restrict__ hidden,
                const float* __restrict__ wq, const float* __restrict__ wk,
                const float* __restrict__ wv,
                float* __restrict__ qo, float* __restrict__ ko,
                float* __restrict__ vo)
{
    __shared__ float As[3 * 128 * AST];
    __shared__ float Bs[3 * 16 * BST];

    const int bn = blockIdx.x, bm = blockIdx.y;
    const float* W; float* C; int N, nh, bl;
    if (bn < 16)      { W = wq; C = qo; N = 2048; nh = NH;  bl = bn; }
    else if (bn < 20) { W = wk; C = ko; N = 512;  nh = NKV; bl = bn - 16; }
    else              { W = wv; C = vo; N = 512;  nh = NKV; bl = bn - 20; }

    const float* Ab = hidden + (size_t)bm * 128 * 2048;
    const float* Wb = W + bl * 128;

    float acc[4][4][4];
#pragma unroll
    for (int i = 0; i < 4; i++)
#pragma unroll
        for (int j = 0; j < 4; j++)
#pragma unroll
            for (int r = 0; r < 4; r++) acc[i][j][r] = 0.f;

    gemm_mainloop(Ab, Wb, N, 2048, acc, As, Bs);

    const int tid = threadIdx.x;
    const int warp = tid >> 5, lane = tid & 31;
    const int g = lane >> 2, t = lane & 3;
    const int wm = warp >> 2, wn = warp & 3;

#pragma unroll
    for (int mt = 0; mt < 4; mt++)
#pragma unroll
        for (int nt = 0; nt < 4; nt++)
#pragma unroll
            for (int ri = 0; ri < 4; ri++) {
                int r = wm * 64 + mt * 16 + g + ((ri >= 2) ? 8 : 0);
                int c = wn * 32 + nt * 8 + 2 * t + (ri & 1);
                int m = bm * 128 + r, n = bl * 128 + c;
                int b_ = m >> 10, s = m & 1023;
                int head = n >> 6, dd = n & 63;
                C[(((size_t)b_ * nh + head) * SS + s) * HD + dd] = acc[mt][nt][ri];
            }
}

// ---------------------------------------------------------------------------
// Plain GEMM (out projection): C[m*N+n] = A @ W.
// ---------------------------------------------------------------------------
__global__ __launch_bounds__(256, 2)
void gemm_kernel(const float* __restrict__ A, const float* __restrict__ W,
                 float* __restrict__ C, int M, int N, int K)
{
    __shared__ float As[3 * 128 * AST];
    __shared__ float Bs[3 * 16 * BST];

    const int bn = blockIdx.x, bm = blockIdx.y;
    const float* Ab = A + (size_t)bm * 128 * K;
    const float* Wb = W + bn * 128;

    float acc[4][4][4];
#pragma unroll
    for (int i = 0; i < 4; i++)
#pragma unroll
        for (int j = 0; j < 4; j++)
#pragma unroll
            for (int r = 0; r < 4; r++) acc[i][j][r] = 0.f;

    gemm_mainloop(Ab, Wb, N, K, acc, As, Bs);

    const int tid = threadIdx.x;
    const int warp = tid >> 5, lane = tid & 31;
    const int g = lane >> 2, t = lane & 3;
    const int wm = warp >> 2, wn = warp & 3;

#pragma unroll
    for (int mt = 0; mt < 4; mt++)
#pragma unroll
        for (int nt = 0; nt < 4; nt++)
#pragma unroll
            for (int ri = 0; ri < 4; ri++) {
                int r = wm * 64 + mt * 16 + g + ((ri >= 2) ? 8 : 0);
                int c = wn * 32 + nt * 8 + 2 * t + (ri & 1);
                int m = bm * 128 + r, n = bn * 128 + c;
                C[(size_t)m * N + n] = acc[mt][nt][ri];
            }
}

// ---------------------------------------------------------------------------
// RoPE in place on (rows, 64) buffer; row % S = sequence position.
// ---------------------------------------------------------------------------
__global__ void rope_kernel(float* __restrict__ buf, int nrows,
                            const float* __restrict__ cosb,
                            const float* __restrict__ sinb)
{
    int idx = blockIdx.x * blockDim.x + threadIdx.x;
    if (idx >= nrows * 32) return;
    int row = idx >> 5;
    int d = idx & 31;
    int s = row & (SS - 1);
    float x1 = buf[(size_t)row * HD + d];
    float x2 = buf[(size_t)row * HD + d + 32];
    float c1 = cosb[s * HD + d],      s1 = sinb[s * HD + d];
    float c2 = cosb[s * HD + d + 32], s2 = sinb[s * HD + d + 32];
    buf[(size_t)row * HD + d]      = x1 * c1 - x2 * s1;
    buf[(size_t)row * HD + d + 32] = x2 * c2 + x1 * s2;
}

// ---------------------------------------------------------------------------
// Scores: e[z,q,k] = exp((Q.K)/8) (masked -> 0), written UNNORMALIZED.
// v2: e-tile staged in the (dead) Ks smem buffer after the mma loop, then
// written with coalesced float4 STGs; per-row partial sums computed in the
// same pass (4 threads/row + shfl), removing the old rp reduction.
// ---------------------------------------------------------------------------
#define QST 68

__global__ __launch_bounds__(256)
void scores_kernel(const float* __restrict__ q, const float* __restrict__ k,
                   const float* __restrict__ mask, float* __restrict__ attn,
                   float* __restrict__ part)
{
    const int kt = blockIdx.x, qt = blockIdx.y, z = blockIdx.z;
    const int b = z >> 5, h = z & 31, kvh = h >> 2;
    const int tid = threadIdx.x;
    float* outp = attn + ((size_t)z * SS + qt * 64) * SS + kt * 64;

    if (kt > qt) { // fully masked tile: post-softmax attn is 0 here
        float4 zero = make_float4(0.f, 0.f, 0.f, 0.f);
#pragma unroll
        for (int i = 0; i < 4; i++) {
            int idx = tid + i * 256;
            int r = idx >> 4, c = (idx & 15) * 4;
            *(float4*)(outp + (size_t)r * SS + c) = zero;
        }
        return;
    }

    const float* Q  = q + (size_t)z * SS * HD + qt * 64 * HD;
    const float* Kp = k + ((size_t)(b * NKV + kvh) * SS + kt * 64) * HD;

    __shared__ unsigned Qs[64 * QST];
    __shared__ unsigned Ks[64 * QST];

#pragma unroll
    for (int l = 0; l < 4; l++) {
        int idx = tid + l * 256;
        int row = idx >> 4, c4 = (idx & 15) * 4;
        float4 qv = *(const float4*)(Q + (size_t)row * HD + c4);
        *(uint4*)&Qs[row * QST + c4] =
            make_uint4(f2tf(qv.x), f2tf(qv.y), f2tf(qv.z), f2tf(qv.w));
        float4 kv = *(const float4*)(Kp + (size_t)row * HD + c4);
        *(uint4*)&Ks[row * QST + c4] =
            make_uint4(f2tf(kv.x), f2tf(kv.y), f2tf(kv.z), f2tf(kv.w));
    }
    __syncthreads();

    const int warp = tid >> 5, lane = tid & 31;
    const int g = lane >> 2, t = lane & 3;
    const int wm = warp >> 2, wn = warp & 3;

    float acc[2][2][4];
#pragma unroll
    for (int i = 0; i < 2; i++)
#pragma unroll
        for (int j = 0; j < 2; j++)
#pragma unroll
            for (int r = 0; r < 4; r++) acc[i][j][r] = 0.f;

#pragma unroll
    for (int kb = 0; kb < 64; kb += 8) {
        unsigned a[2][4], bf[2][2];
#pragma unroll
        for (int mt = 0; mt < 2; mt++) {
            int rb = wm * 32 + mt * 16;
            a[mt][0] = Qs[(rb + g) * QST + kb + t];
            a[mt][1] = Qs[(rb + g + 8) * QST + kb + t];
            a[mt][2] = Qs[(rb + g) * QST + kb + t + 4];
            a[mt][3] = Qs[(rb + g + 8) * QST + kb + t + 4];
        }
#pragma unroll
        for (int nt = 0; nt < 2; nt++) {
            int cb = wn * 16 + nt * 8;
            bf[nt][0] = Ks[(cb + g) * QST + kb + t];
            bf[nt][1] = Ks[(cb + g) * QST + kb + t + 4];
        }
#pragma unroll
        for (int mt = 0; mt < 2; mt++)
#pragma unroll
            for (int nt = 0; nt < 2; nt++)
                mma_tf32(acc[mt][nt], a[mt][0], a[mt][1], a[mt][2], a[mt][3],
                         bf[nt][0], bf[nt][1]);
    }
    __syncthreads();                 // all warps done reading Qs/Ks

    // ---- stage e into the dead Ks buffer ----
    float* Es = (float*)Ks;
#pragma unroll
    for (int mt = 0; mt < 2; mt++)
#pragma unroll
        for (int nt = 0; nt < 2; nt++)
#pragma unroll
            for (int ri = 0; ri < 4; ri++) {
                int r = wm * 32 + mt * 16 + g + ((ri >= 2) ? 8 : 0);
                int c = wn * 16 + nt * 8 + 2 * t + (ri & 1);
                int qg = qt * 64 + r, kg = kt * 64 + c;
                bool ok = (kg <= qg) && (mask[b * SS + kg] == 1.0f);
                Es[r * QST + c] = ok ? __expf(acc[mt][nt][ri] * 0.125f) : 0.f;
            }
    __syncthreads();

    // ---- coalesced float4 store + per-row partial sum (4 threads/row) ----
    {
        const int srow = tid >> 2, q4 = tid & 3;
        const float* src = Es + srow * QST;
        float* dst = outp + (size_t)srow * SS;
        float s = 0.f;
#pragma unroll
        for (int p = 0; p < 4; p++) {
            int ch = q4 + p * 4;
            float4 e4 = *(const float4*)&src[ch * 4];
            s += e4.x + e4.y + e4.z + e4.w;
            *(float4*)(dst + ch * 4) = e4;
        }
        s += __shfl_xor_sync(0xffffffffu, s, 1);
        s += __shfl_xor_sync(0xffffffffu, s, 2);
        if (q4 == 0)
            part[((size_t)z * SS + qt * 64 + srow) * NKT + kt] = s;
    }
}

// ---------------------------------------------------------------------------
// Combine partial sums -> 1/rowsum.
// ---------------------------------------------------------------------------
__global__ void combine_kernel(const float* __restrict__ part,
                               float* __restrict__ inv)
{
    int row = blockIdx.x * blockDim.x + threadIdx.x;
    if (row >= NROWS) return;
    int qt = (row & (SS - 1)) >> 6;
    float s = 0.f;
    for (int kt = 0; kt <= qt; kt++) s += part[(size_t)row * NKT + kt];
    inv[row] = 1.0f / s;
}

// ---------------------------------------------------------------------------
// ctx v2: cp.async double-buffered P/V tiles. Per causal k-tile:
//  - after arrival, stream normalized attn (e*inv) to gmem (coalesced float4)
//  - mma consumes RAW e; ctx accumulators scaled by inv once at epilogue
// ---------------------------------------------------------------------------
#define PST3 68
#define VST3 72
#define CTX_SMEM ((2 * 64 * PST3 + 2 * 64 * VST3 + 64) * 4)

__global__ __launch_bounds__(256)
void ctx_kernel(float* __restrict__ attn, const float* __restrict__ v,
                const float* __restrict__ inv, float* __restrict__ ctx)
{
    extern __shared__ float sm[];
    float* Psm  = sm;                       // 2 x 64 x PST3
    float* Vsm  = sm + 2 * 64 * PST3;       // 2 x 64 x VST3
    float* invs = Vsm + 2 * 64 * VST3;      // 64

    const int qt = 15 - blockIdx.x;         // heavy blocks first
    const int z  = blockIdx.y;
    const int b = z >> 5, h = z & 31, kvh = h >> 2;
    const int tid = threadIdx.x;
    const int warp = tid >> 5, lane = tid & 31;
    const int g = lane >> 2, t = lane & 3;
    const int wm = warp >> 2, wn = warp & 3;

    float* P = attn + ((size_t)z * SS + qt * 64) * SS;
    const float* V = v + (size_t)(b * NKV + kvh) * SS * HD;
    const int nkt = qt + 1;

    if (tid < 64) invs[tid] = inv[(size_t)z * SS + qt * 64 + tid];

    // prologue: tile 0
    {
#pragma unroll
        for (int l = 0; l < 4; l++) {
            int i4 = tid + l * 256;
            int row = i4 >> 4, c4 = (i4 & 15) * 4;
            cpa16(&Psm[row * PST3 + c4], P + (size_t)row * SS + c4);
            cpa16(&Vsm[row * VST3 + c4], V + (size_t)row * HD + c4);
        }
        asm volatile("cp.async.commit_group;");
    }

    float acc[2][2][4];
#pragma unroll
    for (int i = 0; i < 2; i++)
#pragma unroll
        for (int j = 0; j < 2; j++)
#pragma unroll
            for (int r = 0; r < 4; r++) acc[i][j][r] = 0.f;

    for (int kt = 0; kt < nkt; kt++) {
        if (kt + 1 < nkt) {
            float* Pn = Psm + ((kt + 1) & 1) * 64 * PST3;
            float* Vn = Vsm + ((kt + 1) & 1) * 64 * VST3;
            const float* Pg = P + (size_t)(kt + 1) * 64;
            const float* Vg = V + (size_t)(kt + 1) * 64 * HD;
#pragma unroll
            for (int l = 0; l < 4; l++) {
                int i4 = tid + l * 256;
                int row = i4 >> 4, c4 = (i4 & 15) * 4;
                cpa16(&Pn[row * PST3 + c4], Pg + (size_t)row * SS + c4);
                cpa16(&Vn[row * VST3 + c4], Vg + (size_t)row * HD + c4);
            }
            asm volatile("cp.async.commit_group;");
            asm volatile("cp.async.wait_group 1;");
        } else {
            asm volatile("cp.async.wait_group 0;");
        }
        __syncthreads();

        const float* Pc = Psm + (kt & 1) * 64 * PST3;
        const float* Vc = Vsm + (kt & 1) * 64 * VST3;

        // stream normalized attention to gmem (single required write)
#pragma unroll
        for (int l = 0; l < 4; l++) {
            int i4 = tid + l * 256;
            int row = i4 >> 4, c4 = (i4 & 15) * 4;
            float iv = invs[row];
            float4 pv = *(const float4*)&Pc[row * PST3 + c4];
            pv.x *= iv; pv.y *= iv; pv.z *= iv; pv.w *= iv;
            *(float4*)(P + (size_t)row * SS + kt * 64 + c4) = pv;
        }

        // ctx += e_tile . V_tile (raw e; inv applied at epilogue)
#pragma unroll
        for (int kb = 0; kb < 64; kb += 8) {
            unsigned a[2][4], bf[2][2];
#pragma unroll
            for (int mt = 0; mt < 2; mt++) {
                int rb = wm * 32 + mt * 16;
                a[mt][0] = f2tf(Pc[(rb + g) * PST3 + kb + t]);
                a[mt][1] = f2tf(Pc[(rb + g + 8) * PST3 + kb + t]);
                a[mt][2] = f2tf(Pc[(rb + g) * PST3 + kb + t + 4]);
                a[mt][3] = f2tf(Pc[(rb + g + 8) * PST3 + kb + t + 4]);
            }
#pragma unroll
            for (int nt = 0; nt < 2; nt++) {
                int cb = wn * 16 + nt * 8;
                bf[nt][0] = f2tf(Vc[(kb + t) * VST3 + cb + g]);
                bf[nt][1] = f2tf(Vc[(kb + t + 4) * VST3 + cb + g]);
            }
#pragma unroll
            for (int mt = 0; mt < 2; mt++)
#pragma unroll
                for (int nt = 0; nt < 2; nt++)
                    mma_tf32(acc[mt][nt], a[mt][0], a[mt][1], a[mt][2], a[mt][3],
                             bf[nt][0], bf[nt][1]);
        }
        __syncthreads();
    }

#pragma unroll
    for (int mt = 0; mt < 2; mt++)
#pragma unroll
        for (int nt = 0; nt < 2; nt++)
#pragma unroll
            for (int ri = 0; ri < 4; ri++) {
                int r = wm * 32 + mt * 16 + g + ((ri >= 2) ? 8 : 0);
                int c = wn * 16 + nt * 8 + 2 * t + (ri & 1);
                int qg = qt * 64 + r;
                ctx[((size_t)b * SS + qg) * HID + h * HD + c] =
                    acc[mt][nt][ri] * invs[r];
            }
}

// ---------------------------------------------------------------------------
extern "C" void kernel_launch(void* const* d_in, const int* in_sizes, int n_in,
                              void* d_out, int out_size)
{
    const float* hidden = (const float*)d_in[0];
    const float* mask   = (const float*)d_in[1];
    const float* cosb   = (const float*)d_in[2];
    const float* sinb   = (const float*)d_in[3];
    const float* wq     = (const float*)d_in[4];
    const float* wk     = (const float*)d_in[5];
    const float* wv     = (const float*)d_in[6];
    const float* wo     = (const float*)d_in[7];

    float* outp = (float*)d_out;

    float *qp, *kp, *vp, *cp, *pp, *ip;
    cudaGetSymbolAddress((void**)&qp, g_q);
    cudaGetSymbolAddress((void**)&kp, g_k);
    cudaGetSymbolAddress((void**)&vp, g_v);
    cudaGetSymbolAddress((void**)&cp, g_ctx);
    cudaGetSymbolAddress((void**)&pp, g_part);
    cudaGetSymbolAddress((void**)&ip, g_inv);

    float* attnp;
    if ((size_t)out_size >= OUT_ELEMS + ATTN_ELEMS) {
        attnp = outp + OUT_ELEMS;
    } else {
        cudaGetSymbolAddress((void**)&attnp, g_attn_fallback);
    }

    cudaFuncSetAttribute(ctx_kernel,
                         cudaFuncAttributeMaxDynamicSharedMemorySize, CTX_SMEM);

    // 1) fused QKV projection (3-stage cp.async pipelined tf32)
    qkv_kernel<<<dim3(24, 16), 256>>>(hidden, wq, wk, wv, qp, kp, vp);

    // 2) RoPE on q and k
    rope_kernel<<<(BB * NH * SS * 32) / 256, 256>>>(qp, BB * NH * SS, cosb, sinb);
    rope_kernel<<<(BB * NKV * SS * 32) / 256, 256>>>(kp, BB * NKV * SS, cosb, sinb);

    // 3) scores -> unnormalized exp (staged float4 stores) + partial sums
    scores_kernel<<<dim3(16, 16, BB * NH), 256>>>(qp, kp, mask, attnp, pp);

    // 4) combine partials -> 1/rowsum
    combine_kernel<<<NROWS / 256, 256>>>(pp, ip);

    // 5) ctx v2: pipelined attn normalize + P@V
    ctx_kernel<<<dim3(16, BB * NH), 256, CTX_SMEM>>>(attnp, vp, ip, cp);

    // 6) out = ctx @ wo
    gemm_kernel<<<dim3(16, 16), 256>>>(cp, wo, outp, 2048, 2048, 2048);
}